// round 1
// baseline (speedup 1.0000x reference)
#include <cuda_runtime.h>
#include <math.h>

#define BB 64
#define S1 513
#define SS 512
#define HD 768
#define NSTATE 4
#define ST_START 2
#define ST_STOP 3

// ---- scratch (static device globals; no runtime alloc) ----
__device__ __align__(16) float g_feats[BB * SS * 4];   // (b, s, t) float4 rows
__device__ float g_logits[BB * 2];
__device__ float g_Z[BB];
__device__ float g_gold[BB];

// out layout (float32):
// [0,64)            isqa_pred
// [64, 32832)       crf_pred (b*512+s)
// [32832]           isqa_loss
// [32833]           crf_loss
// [32834, 65602)    tags (b*512+s)
// [65602, 65666)    IsQA
#define OFF_PRED   0
#define OFF_CRF    64
#define OFF_ILOSS  32832
#define OFF_CLOSS  32833
#define OFF_TAGS   32834
#define OFF_ISQA   65602

// =====================================================================
// Kernel 1: feats[b,s-1,t] = emb[b,s,:] . crf_W[t,:] + crf_b[t]  (s>=1)
//           logits[b,c]    = emb[b,0,:] . fc2_W[c,:] + fc2_b[c]
// one warp per (b,s) row; memory-bound (reads 100.8 MB of emb)
// =====================================================================
__global__ void k_feats(const float* __restrict__ emb,
                        const float* __restrict__ fc2W, const float* __restrict__ fc2b,
                        const float* __restrict__ crfW, const float* __restrict__ crfb)
{
    int gw = (blockIdx.x * blockDim.x + threadIdx.x) >> 5;
    int lane = threadIdx.x & 31;
    if (gw >= BB * S1) return;
    int b = gw / S1;
    int s = gw - b * S1;

    const float4* e4 = reinterpret_cast<const float4*>(emb) + (size_t)gw * (HD / 4);

    if (s == 0) {
        const float4* w0 = reinterpret_cast<const float4*>(fc2W);
        const float4* w1 = w0 + (HD / 4);
        float a0 = 0.f, a1 = 0.f;
        #pragma unroll
        for (int k = 0; k < 6; k++) {
            float4 e = e4[k * 32 + lane];
            float4 x = w0[k * 32 + lane];
            float4 y = w1[k * 32 + lane];
            a0 += e.x * x.x + e.y * x.y + e.z * x.z + e.w * x.w;
            a1 += e.x * y.x + e.y * y.y + e.z * y.z + e.w * y.w;
        }
        #pragma unroll
        for (int off = 16; off; off >>= 1) {
            a0 += __shfl_xor_sync(~0u, a0, off);
            a1 += __shfl_xor_sync(~0u, a1, off);
        }
        if (lane == 0) {
            g_logits[b * 2 + 0] = a0 + fc2b[0];
            g_logits[b * 2 + 1] = a1 + fc2b[1];
        }
    } else {
        const float4* w = reinterpret_cast<const float4*>(crfW);
        float a0 = 0.f, a1 = 0.f, a2 = 0.f, a3 = 0.f;
        #pragma unroll
        for (int k = 0; k < 6; k++) {
            int idx = k * 32 + lane;
            float4 e  = e4[idx];
            float4 t0 = w[0 * 192 + idx];
            float4 t1 = w[1 * 192 + idx];
            float4 t2 = w[2 * 192 + idx];
            float4 t3 = w[3 * 192 + idx];
            a0 += e.x * t0.x + e.y * t0.y + e.z * t0.z + e.w * t0.w;
            a1 += e.x * t1.x + e.y * t1.y + e.z * t1.z + e.w * t1.w;
            a2 += e.x * t2.x + e.y * t2.y + e.z * t2.z + e.w * t2.w;
            a3 += e.x * t3.x + e.y * t3.y + e.z * t3.z + e.w * t3.w;
        }
        #pragma unroll
        for (int off = 16; off; off >>= 1) {
            a0 += __shfl_xor_sync(~0u, a0, off);
            a1 += __shfl_xor_sync(~0u, a1, off);
            a2 += __shfl_xor_sync(~0u, a2, off);
            a3 += __shfl_xor_sync(~0u, a3, off);
        }
        if (lane == 0) {
            float4* F = reinterpret_cast<float4*>(g_feats);
            F[b * SS + (s - 1)] = make_float4(a0 + crfb[0], a1 + crfb[1],
                                              a2 + crfb[2], a3 + crfb[3]);
        }
    }
}

// 4-element map composition: r(x) = f(h(x)); maps packed one byte per entry
__device__ __forceinline__ unsigned compose_map(unsigned f, unsigned h)
{
    unsigned r = 0;
    #pragma unroll
    for (int x = 0; x < 4; x++) {
        unsigned hx = (h >> (8 * x)) & 3u;
        unsigned fx = (f >> (8 * hx)) & 3u;
        r |= fx << (8 * x);
    }
    return r;
}

// =====================================================================
// Kernel 2: 128 one-warp blocks.
//   blocks [0,64):   forward (log-partition, linear space w/ renorm) + gold
//   blocks [64,128): viterbi forward + parallel-suffix-scan backtrack
// =====================================================================
__global__ void k_crf(const int* __restrict__ asl,
                      const float* __restrict__ trans,
                      float* __restrict__ out)
{
    int b = blockIdx.x & 63;
    bool vit = blockIdx.x >= 64;
    int lane = threadIdx.x;

    float T[4][4];
    #pragma unroll
    for (int i = 0; i < 4; i++)
        #pragma unroll
        for (int j = 0; j < 4; j++)
            T[i][j] = __ldg(&trans[i * 4 + j]);

    const float4* F = reinterpret_cast<const float4*>(g_feats) + b * SS;
    const int* tg = asl + b * S1 + 1;  // tags[b][s], s in [0,512)

    if (!vit) {
        // ---------------- forward + gold ----------------
        __shared__ float4 sef[SS];  // exp(feats)

        float gpart = 0.f;
        for (int i = lane; i < SS; i += 32) {
            float4 f = F[i];
            sef[i] = make_float4(expf(f.x), expf(f.y), expf(f.z), expf(f.w));
            int tc = tg[i];
            // emit
            gpart += tc ? f.y : f.x;
            // transitions
            float tval;
            if (i == 0) {
                tval = tc ? T[ST_START][1] : T[ST_START][0];
            } else {
                int tp = tg[i - 1];
                tval = tp ? (tc ? T[1][1] : T[1][0]) : (tc ? T[0][1] : T[0][0]);
            }
            gpart += tval;
            if (i == SS - 1) gpart += tc ? T[1][ST_STOP] : T[0][ST_STOP];
        }
        #pragma unroll
        for (int off = 16; off; off >>= 1)
            gpart += __shfl_xor_sync(~0u, gpart, off);
        __syncwarp();

        if (lane == 0) {
            g_gold[b] = gpart;

            float E[4][4];
            #pragma unroll
            for (int i = 0; i < 4; i++)
                #pragma unroll
                for (int j = 0; j < 4; j++)
                    E[i][j] = expf(T[i][j]);

            float4 f0 = sef[0];
            float a0 = f0.x * E[ST_START][0];
            float a1 = f0.y * E[ST_START][1];
            float a2 = f0.z * E[ST_START][2];
            float a3 = f0.w * E[ST_START][3];
            float logacc = 0.f;
            // initial renorm
            {
                float m = fmaxf(fmaxf(a0, a1), fmaxf(a2, a3));
                float inv = 1.0f / m;
                a0 *= inv; a1 *= inv; a2 *= inv; a3 *= inv;
                logacc += logf(m);
            }
            #pragma unroll 4
            for (int s = 1; s < SS; s++) {
                float4 ef = sef[s];
                float n0 = ((a0 * E[0][0] + a1 * E[1][0]) + (a2 * E[2][0] + a3 * E[3][0])) * ef.x;
                float n1 = ((a0 * E[0][1] + a1 * E[1][1]) + (a2 * E[2][1] + a3 * E[3][1])) * ef.y;
                float n2 = ((a0 * E[0][2] + a1 * E[1][2]) + (a2 * E[2][2] + a3 * E[3][2])) * ef.z;
                float n3 = ((a0 * E[0][3] + a1 * E[1][3]) + (a2 * E[2][3] + a3 * E[3][3])) * ef.w;
                a0 = n0; a1 = n1; a2 = n2; a3 = n3;
                if ((s & 7) == 0) {
                    float m = fmaxf(fmaxf(a0, a1), fmaxf(a2, a3));
                    float inv = 1.0f / m;
                    a0 *= inv; a1 *= inv; a2 *= inv; a3 *= inv;
                    logacc += logf(m);
                }
            }
            float zs = a0 * E[0][ST_STOP] + a1 * E[1][ST_STOP]
                     + a2 * E[2][ST_STOP] + a3 * E[3][ST_STOP];
            g_Z[b] = logacc + logf(zs);
        }
    } else {
        // ---------------- viterbi ----------------
        __shared__ float4 sfv[SS];
        __shared__ unsigned sbp[SS];   // bp[s-1] packed: byte j = argmax predecessor of state j
        __shared__ int s_last;

        for (int i = lane; i < SS; i += 32) sfv[i] = F[i];
        __syncwarp();

        if (lane == 0) {
            float4 f0 = sfv[0];
            float d0 = f0.x + T[ST_START][0];
            float d1 = f0.y + T[ST_START][1];
            float d2 = f0.z + T[ST_START][2];
            float d3 = f0.w + T[ST_START][3];
            for (int s = 1; s < SS; s++) {
                float4 f = sfv[s];
                unsigned bp = 0;
                float nd0, nd1, nd2, nd3;
                #define VSTEP(J, FJ, ND)                                          \
                {                                                                 \
                    float v0 = d0 + T[0][J], v1 = d1 + T[1][J];                   \
                    float v2 = d2 + T[2][J], v3 = d3 + T[3][J];                   \
                    float m01 = v0; int i01 = 0;                                  \
                    if (v1 > m01) { m01 = v1; i01 = 1; }                          \
                    float m23 = v2; int i23 = 2;                                  \
                    if (v3 > m23) { m23 = v3; i23 = 3; }                          \
                    float mm = m01; int ii = i01;                                 \
                    if (m23 > mm) { mm = m23; ii = i23; }                         \
                    ND = mm + FJ;                                                 \
                    bp |= ((unsigned)ii) << (8 * J);                              \
                }
                VSTEP(0, f.x, nd0)
                VSTEP(1, f.y, nd1)
                VSTEP(2, f.z, nd2)
                VSTEP(3, f.w, nd3)
                #undef VSTEP
                sbp[s - 1] = bp;
                d0 = nd0; d1 = nd1; d2 = nd2; d3 = nd3;
            }
            // last tag: first argmax of d_j + T[j][STOP]
            float w0 = d0 + T[0][ST_STOP], w1 = d1 + T[1][ST_STOP];
            float w2 = d2 + T[2][ST_STOP], w3 = d3 + T[3][ST_STOP];
            float m01 = w0; int i01 = 0; if (w1 > m01) { m01 = w1; i01 = 1; }
            float m23 = w2; int i23 = 2; if (w3 > m23) { m23 = w3; i23 = 3; }
            int ii = i01; if (m23 > m01) ii = i23;
            s_last = ii;
        }
        __syncwarp();

        // parallel suffix scan of map compositions: path[t] = (f_t o ... o f_510)(last)
        const unsigned IDMAP = 0x03020100u;
        int last = s_last;
        int base = lane * 16;
        unsigned locals[16];
        unsigned run = IDMAP;
        #pragma unroll
        for (int k = 15; k >= 0; k--) {
            int t = base + k;
            unsigned f = (t < SS - 1) ? sbp[t] : IDMAP;
            run = compose_map(f, run);
            locals[k] = run;
        }
        unsigned scanv = locals[0];
        #pragma unroll
        for (int d = 1; d < 32; d <<= 1) {
            unsigned up = __shfl_down_sync(~0u, scanv, d);
            if (lane + d < 32) scanv = compose_map(scanv, up);
        }
        unsigned excl = __shfl_down_sync(~0u, scanv, 1);
        if (lane == 31) excl = IDMAP;
        int e = (excl >> (8 * last)) & 3;

        float* po = out + OFF_CRF + b * SS;
        #pragma unroll
        for (int k = 0; k < 16; k++) {
            int t = base + k;
            if (t < SS - 1) po[t] = (float)((locals[k] >> (8 * e)) & 3u);
        }
        if (lane == 31) po[SS - 1] = (float)last;
    }
}

// =====================================================================
// Kernel 3: losses, preds, copies
// =====================================================================
__global__ void k_final(const int* __restrict__ asl, const int* __restrict__ isqa,
                        float* __restrict__ out)
{
    int idx = blockIdx.x * blockDim.x + threadIdx.x;
    if (idx < BB * SS) {
        int b = idx >> 9;
        int s = idx & 511;
        out[OFF_TAGS + idx] = (float)asl[b * S1 + 1 + s];
    }
    if (idx < BB) {
        out[OFF_ISQA + idx] = (float)isqa[idx];
        float l0 = g_logits[idx * 2 + 0];
        float l1 = g_logits[idx * 2 + 1];
        out[OFF_PRED + idx] = (l1 > l0) ? 1.0f : 0.0f;
    }
    if (idx == 0) {
        float iloss = 0.f, closs = 0.f;
        for (int b2 = 0; b2 < BB; b2++) {
            float l0 = g_logits[b2 * 2 + 0];
            float l1 = g_logits[b2 * 2 + 1];
            float m = fmaxf(l0, l1);
            float lse = m + logf(expf(l0 - m) + expf(l1 - m));
            float ly = isqa[b2] ? l1 : l0;
            iloss += lse - ly;
            closs += g_Z[b2] - g_gold[b2];
        }
        out[OFF_ILOSS] = iloss * (1.0f / BB);
        out[OFF_CLOSS] = closs * (1.0f / BB);
    }
}

extern "C" void kernel_launch(void* const* d_in, const int* in_sizes, int n_in,
                              void* d_out, int out_size)
{
    const float* emb  = (const float*)d_in[0];
    const int*   asl  = (const int*)d_in[1];
    const int*   isqa = (const int*)d_in[2];
    const float* fc2W = (const float*)d_in[3];
    const float* fc2b = (const float*)d_in[4];
    const float* crfW = (const float*)d_in[5];
    const float* crfb = (const float*)d_in[6];
    const float* trans = (const float*)d_in[7];
    float* out = (float*)d_out;

    int rows = BB * S1;                 // 32832 rows, one warp each
    int threads = 256;                  // 8 warps / block
    int blocks = (rows * 32 + threads - 1) / threads;
    k_feats<<<blocks, threads>>>(emb, fc2W, fc2b, crfW, crfb);
    k_crf<<<128, 32>>>(asl, trans, out);
    k_final<<<(BB * SS + 255) / 256, 256>>>(asl, isqa, out);
}

// round 2
// speedup vs baseline: 1.1455x; 1.1455x over previous
#include <cuda_runtime.h>
#include <math.h>

#define BB 64
#define S1 513
#define SS 512
#define HD 768
#define ST_START 2
#define ST_STOP 3
#define NEGINF (-1e30f)

// ---- scratch ----
__device__ __align__(16) float g_feats[BB * SS * 4];
__device__ float g_logits[BB * 2];
__device__ float g_Z[BB];
__device__ float g_gold[BB];

// out layout (float32)
#define OFF_PRED   0
#define OFF_CRF    64
#define OFF_ILOSS  32832
#define OFF_CLOSS  32833
#define OFF_TAGS   32834
#define OFF_ISQA   65602

// =====================================================================
// Kernel 1: feats + cls logits. One warp per 4 rows (weight reuse x4).
// =====================================================================
__global__ void k_feats(const float* __restrict__ emb,
                        const float* __restrict__ fc2W, const float* __restrict__ fc2b,
                        const float* __restrict__ crfW, const float* __restrict__ crfb)
{
    int w = (blockIdx.x * blockDim.x + threadIdx.x) >> 5;
    int lane = threadIdx.x & 31;
    if (w >= BB * 129) return;
    int b = w / 129;
    int g = w - b * 129;
    const float4* emb4 = reinterpret_cast<const float4*>(emb);

    if (g == 128) {
        // CLS row -> fc2 logits
        const float4* e4 = emb4 + (size_t)(b * S1) * (HD / 4);
        const float4* w0 = reinterpret_cast<const float4*>(fc2W);
        const float4* w1 = w0 + (HD / 4);
        float a0 = 0.f, a1 = 0.f;
        #pragma unroll
        for (int k = 0; k < 6; k++) {
            int idx = k * 32 + lane;
            float4 e = e4[idx];
            float4 x = w0[idx];
            float4 y = w1[idx];
            a0 += e.x * x.x + e.y * x.y + e.z * x.z + e.w * x.w;
            a1 += e.x * y.x + e.y * y.y + e.z * y.z + e.w * y.w;
        }
        #pragma unroll
        for (int off = 16; off; off >>= 1) {
            a0 += __shfl_xor_sync(~0u, a0, off);
            a1 += __shfl_xor_sync(~0u, a1, off);
        }
        if (lane == 0) {
            g_logits[b * 2 + 0] = a0 + fc2b[0];
            g_logits[b * 2 + 1] = a1 + fc2b[1];
        }
    } else {
        int row = b * S1 + 1 + g * 4;
        const float4* e4 = emb4 + (size_t)row * (HD / 4);
        const float4* wp = reinterpret_cast<const float4*>(crfW);
        float acc[4][4];
        #pragma unroll
        for (int r = 0; r < 4; r++)
            #pragma unroll
            for (int t = 0; t < 4; t++) acc[r][t] = 0.f;

        #pragma unroll
        for (int k = 0; k < 6; k++) {
            int idx = k * 32 + lane;
            float4 w0 = wp[idx];
            float4 w1 = wp[192 + idx];
            float4 w2 = wp[384 + idx];
            float4 w3 = wp[576 + idx];
            #pragma unroll
            for (int r = 0; r < 4; r++) {
                float4 e = e4[r * 192 + idx];
                acc[r][0] += e.x * w0.x + e.y * w0.y + e.z * w0.z + e.w * w0.w;
                acc[r][1] += e.x * w1.x + e.y * w1.y + e.z * w1.z + e.w * w1.w;
                acc[r][2] += e.x * w2.x + e.y * w2.y + e.z * w2.z + e.w * w2.w;
                acc[r][3] += e.x * w3.x + e.y * w3.y + e.z * w3.z + e.w * w3.w;
            }
        }
        #pragma unroll
        for (int r = 0; r < 4; r++)
            #pragma unroll
            for (int t = 0; t < 4; t++)
                #pragma unroll
                for (int off = 16; off; off >>= 1)
                    acc[r][t] += __shfl_xor_sync(~0u, acc[r][t], off);
        if (lane == 0) {
            float b0 = crfb[0], b1 = crfb[1], b2 = crfb[2], b3 = crfb[3];
            float4* Fo = reinterpret_cast<float4*>(g_feats) + (b * SS + g * 4);
            #pragma unroll
            for (int r = 0; r < 4; r++)
                Fo[r] = make_float4(acc[r][0] + b0, acc[r][1] + b1,
                                    acc[r][2] + b2, acc[r][3] + b3);
        }
    }
}

// ---------- small helpers ----------
__device__ __forceinline__ void mp_mul(const float* A, const float* B, float* C)
{   // C = A (then) B in max-plus; row-vector convention v' = v*A*B
    #pragma unroll
    for (int i = 0; i < 4; i++)
        #pragma unroll
        for (int j = 0; j < 4; j++) {
            float m = A[i*4+0] + B[0*4+j];
            m = fmaxf(m, A[i*4+1] + B[1*4+j]);
            m = fmaxf(m, A[i*4+2] + B[2*4+j]);
            m = fmaxf(m, A[i*4+3] + B[3*4+j]);
            C[i*4+j] = m;
        }
}
__device__ __forceinline__ void lin_mul(const float* A, const float* B, float* C)
{
    #pragma unroll
    for (int i = 0; i < 4; i++)
        #pragma unroll
        for (int j = 0; j < 4; j++)
            C[i*4+j] = A[i*4+0]*B[0*4+j] + A[i*4+1]*B[1*4+j]
                     + A[i*4+2]*B[2*4+j] + A[i*4+3]*B[3*4+j];
}
__device__ __forceinline__ void cp16(float* d, const float* s)
{
    #pragma unroll
    for (int t = 0; t < 16; t++) d[t] = s[t];
}
__device__ __forceinline__ void renorm16(float* M, float& logacc)
{
    float m = M[0];
    #pragma unroll
    for (int t = 1; t < 16; t++) m = fmaxf(m, M[t]);
    float inv = 1.0f / m;
    #pragma unroll
    for (int t = 0; t < 16; t++) M[t] *= inv;
    logacc += logf(m);
}

// =====================================================================
// Kernel 2: 128 one-warp blocks.
//   blocks [0,64):   log-partition (parallel matrix reduction) + gold
//   blocks [64,128): viterbi via max-plus prefix+suffix scans
// =====================================================================
__global__ void k_crf(const int* __restrict__ asl,
                      const float* __restrict__ trans,
                      float* __restrict__ out)
{
    int b = blockIdx.x & 63;
    bool vit = blockIdx.x >= 64;
    int lane = threadIdx.x;

    float T[16];
    #pragma unroll
    for (int t = 0; t < 16; t++) T[t] = __ldg(&trans[t]);

    const float4* F4 = reinterpret_cast<const float4*>(g_feats) + b * SS;

    if (!vit) {
        // ---------- gold score (warp-parallel) ----------
        const int* tg = asl + b * S1 + 1;
        float gpart = 0.f;
        for (int i = lane; i < SS; i += 32) {
            float4 f = F4[i];
            int tc = tg[i];
            gpart += tc ? f.y : f.x;
            float tval;
            if (i == 0) tval = tc ? T[ST_START*4+1] : T[ST_START*4+0];
            else {
                int tp = tg[i - 1];
                tval = tp ? (tc ? T[1*4+1] : T[1*4+0]) : (tc ? T[0*4+1] : T[0*4+0]);
            }
            gpart += tval;
            if (i == SS - 1) gpart += tc ? T[1*4+ST_STOP] : T[0*4+ST_STOP];
        }
        #pragma unroll
        for (int off = 16; off; off >>= 1)
            gpart += __shfl_xor_sync(~0u, gpart, off);
        if (lane == 0) g_gold[b] = gpart;

        // ---------- Z: linear-space matrix reduction w/ renorm ----------
        float E[16];
        #pragma unroll
        for (int t = 0; t < 16; t++) E[t] = expf(T[t]);

        float M[16];
        #pragma unroll
        for (int t = 0; t < 16; t++) M[t] = 0.f;
        M[0] = M[5] = M[10] = M[15] = 1.f;
        float logacc = 0.f;

        #pragma unroll
        for (int k = 0; k < 16; k++) {
            int s = lane * 16 + k;
            if (s > 0) {
                float4 f = F4[s];
                float ef[4] = {expf(f.x), expf(f.y), expf(f.z), expf(f.w)};
                float C[16];
                #pragma unroll
                for (int i = 0; i < 4; i++)
                    #pragma unroll
                    for (int j = 0; j < 4; j++)
                        C[i*4+j] = (M[i*4+0]*E[0*4+j] + M[i*4+1]*E[1*4+j]
                                  + M[i*4+2]*E[2*4+j] + M[i*4+3]*E[3*4+j]) * ef[j];
                cp16(M, C);
                if ((k & 3) == 3) renorm16(M, logacc);
            }
        }
        renorm16(M, logacc);

        // ordered XOR-butterfly reduction (non-commutative, block-aligned)
        #pragma unroll
        for (int d = 1; d < 32; d <<= 1) {
            float O[16];
            #pragma unroll
            for (int t = 0; t < 16; t++) O[t] = __shfl_xor_sync(~0u, M[t], d);
            float ol = __shfl_xor_sync(~0u, logacc, d);
            float C[16];
            if (lane & d) lin_mul(O, M, C);
            else          lin_mul(M, O, C);
            cp16(M, C);
            logacc += ol;
            renorm16(M, logacc);
        }

        if (lane == 0) {
            float4 f0 = F4[0];
            float v0[4] = {expf(f0.x)*E[ST_START*4+0], expf(f0.y)*E[ST_START*4+1],
                           expf(f0.z)*E[ST_START*4+2], expf(f0.w)*E[ST_START*4+3]};
            float zs = 0.f;
            #pragma unroll
            for (int j = 0; j < 4; j++) {
                float vj = v0[0]*M[0*4+j] + v0[1]*M[1*4+j]
                         + v0[2]*M[2*4+j] + v0[3]*M[3*4+j];
                zs += vj * E[j*4+ST_STOP];
            }
            g_Z[b] = logf(zs) + logacc;
        }
    } else {
        // ---------- viterbi: prefix+suffix max-plus scans ----------
        __shared__ float4 sf[SS];
        __shared__ float4 sd[SS];
        for (int i = lane; i < SS; i += 32) sf[i] = F4[i];
        __syncwarp();

        // local product P = A_{16L} x ... x A_{16L+15}   (A_0 := identity)
        float P[16];
        #pragma unroll
        for (int t = 0; t < 16; t++) P[t] = NEGINF;
        P[0] = P[5] = P[10] = P[15] = 0.f;
        #pragma unroll
        for (int k = 0; k < 16; k++) {
            int s = lane * 16 + k;
            if (s > 0) {
                float4 f = sf[s];
                float ff[4] = {f.x, f.y, f.z, f.w};
                float C[16];
                #pragma unroll
                for (int i = 0; i < 4; i++)
                    #pragma unroll
                    for (int j = 0; j < 4; j++) {
                        float m = P[i*4+0] + T[0*4+j];
                        m = fmaxf(m, P[i*4+1] + T[1*4+j]);
                        m = fmaxf(m, P[i*4+2] + T[2*4+j]);
                        m = fmaxf(m, P[i*4+3] + T[3*4+j]);
                        C[i*4+j] = m + ff[j];
                    }
                cp16(P, C);
            }
        }

        // inclusive prefix scan (Hillis-Steele), then exclusive
        float S[16];
        cp16(S, P);
        #pragma unroll
        for (int d = 1; d < 32; d <<= 1) {
            float U[16];
            #pragma unroll
            for (int t = 0; t < 16; t++) U[t] = __shfl_up_sync(~0u, S[t], d);
            if (lane >= d) {
                float C[16];
                mp_mul(U, S, C);
                cp16(S, C);
            }
        }
        float Epre[16];
        #pragma unroll
        for (int t = 0; t < 16; t++) Epre[t] = __shfl_up_sync(~0u, S[t], 1);
        if (lane == 0) {
            #pragma unroll
            for (int t = 0; t < 16; t++) Epre[t] = NEGINF;
            Epre[0] = Epre[5] = Epre[10] = Epre[15] = 0.f;
        }

        // delta base = delta0 * Epre ; then per-step forward emit into sd
        float4 f0 = sf[0];
        float d0[4] = {f0.x + T[ST_START*4+0], f0.y + T[ST_START*4+1],
                       f0.z + T[ST_START*4+2], f0.w + T[ST_START*4+3]};
        float v[4];
        #pragma unroll
        for (int j = 0; j < 4; j++) {
            float m = d0[0] + Epre[0*4+j];
            m = fmaxf(m, d0[1] + Epre[1*4+j]);
            m = fmaxf(m, d0[2] + Epre[2*4+j]);
            m = fmaxf(m, d0[3] + Epre[3*4+j]);
            v[j] = m;
        }
        #pragma unroll
        for (int k = 0; k < 16; k++) {
            int s = lane * 16 + k;
            if (s > 0) {
                float4 f = sf[s];
                float nv0 = fmaxf(fmaxf(v[0]+T[0*4+0], v[1]+T[1*4+0]),
                                  fmaxf(v[2]+T[2*4+0], v[3]+T[3*4+0])) + f.x;
                float nv1 = fmaxf(fmaxf(v[0]+T[0*4+1], v[1]+T[1*4+1]),
                                  fmaxf(v[2]+T[2*4+1], v[3]+T[3*4+1])) + f.y;
                float nv2 = fmaxf(fmaxf(v[0]+T[0*4+2], v[1]+T[1*4+2]),
                                  fmaxf(v[2]+T[2*4+2], v[3]+T[3*4+2])) + f.z;
                float nv3 = fmaxf(fmaxf(v[0]+T[0*4+3], v[1]+T[1*4+3]),
                                  fmaxf(v[2]+T[2*4+3], v[3]+T[3*4+3])) + f.w;
                v[0] = nv0; v[1] = nv1; v[2] = nv2; v[3] = nv3;
            }
            sd[s] = make_float4(v[0], v[1], v[2], v[3]);
        }
        __syncwarp();

        // inclusive suffix scan of P, then exclusive (Qex)
        cp16(S, P);
        #pragma unroll
        for (int d = 1; d < 32; d <<= 1) {
            float D[16];
            #pragma unroll
            for (int t = 0; t < 16; t++) D[t] = __shfl_down_sync(~0u, S[t], d);
            if (lane + d < 32) {
                float C[16];
                mp_mul(S, D, C);
                cp16(S, C);
            }
        }
        float Qex[16];
        #pragma unroll
        for (int t = 0; t < 16; t++) Qex[t] = __shfl_down_sync(~0u, S[t], 1);
        if (lane == 31) {
            #pragma unroll
            for (int t = 0; t < 16; t++) Qex[t] = NEGINF;
            Qex[0] = Qex[5] = Qex[10] = Qex[15] = 0.f;
        }

        // beta at s = 16L+15
        float r0[4] = {T[0*4+ST_STOP], T[1*4+ST_STOP], T[2*4+ST_STOP], T[3*4+ST_STOP]};
        float bb[4];
        #pragma unroll
        for (int i = 0; i < 4; i++) {
            float m = Qex[i*4+0] + r0[0];
            m = fmaxf(m, Qex[i*4+1] + r0[1]);
            m = fmaxf(m, Qex[i*4+2] + r0[2]);
            m = fmaxf(m, Qex[i*4+3] + r0[3]);
            bb[i] = m;
        }

        // backward: tag_s = argmax(delta_s + beta_s); update beta with A_s
        float* po = out + OFF_CRF + b * SS;
        #pragma unroll
        for (int k = 15; k >= 0; k--) {
            int s = lane * 16 + k;
            float4 dd = sd[s];
            float dv0 = dd.x + bb[0], dv1 = dd.y + bb[1];
            float dv2 = dd.z + bb[2], dv3 = dd.w + bb[3];
            int tsel = 0; float m = dv0;
            if (dv1 > m) { m = dv1; tsel = 1; }
            if (dv2 > m) { m = dv2; tsel = 2; }
            if (dv3 > m) { m = dv3; tsel = 3; }
            po[s] = (float)tsel;
            if (k > 0) {
                float4 f = sf[s];
                float u0 = f.x + bb[0], u1 = f.y + bb[1];
                float u2 = f.z + bb[2], u3 = f.w + bb[3];
                float nb0 = fmaxf(fmaxf(T[0*4+0]+u0, T[0*4+1]+u1), fmaxf(T[0*4+2]+u2, T[0*4+3]+u3));
                float nb1 = fmaxf(fmaxf(T[1*4+0]+u0, T[1*4+1]+u1), fmaxf(T[1*4+2]+u2, T[1*4+3]+u3));
                float nb2 = fmaxf(fmaxf(T[2*4+0]+u0, T[2*4+1]+u1), fmaxf(T[2*4+2]+u2, T[2*4+3]+u3));
                float nb3 = fmaxf(fmaxf(T[3*4+0]+u0, T[3*4+1]+u1), fmaxf(T[3*4+2]+u2, T[3*4+3]+u3));
                bb[0] = nb0; bb[1] = nb1; bb[2] = nb2; bb[3] = nb3;
            }
        }
    }
}

// =====================================================================
// Kernel 3: losses, preds, copies
// =====================================================================
__global__ void k_final(const int* __restrict__ asl, const int* __restrict__ isqa,
                        float* __restrict__ out)
{
    int idx = blockIdx.x * blockDim.x + threadIdx.x;
    if (idx < BB * SS) {
        int b = idx >> 9;
        int s = idx & 511;
        out[OFF_TAGS + idx] = (float)asl[b * S1 + 1 + s];
    }
    if (idx < BB) {
        out[OFF_ISQA + idx] = (float)isqa[idx];
        float l0 = g_logits[idx * 2 + 0];
        float l1 = g_logits[idx * 2 + 1];
        out[OFF_PRED + idx] = (l1 > l0) ? 1.0f : 0.0f;
    }
    if (idx == 0) {
        float iloss = 0.f, closs = 0.f;
        for (int b2 = 0; b2 < BB; b2++) {
            float l0 = g_logits[b2 * 2 + 0];
            float l1 = g_logits[b2 * 2 + 1];
            float m = fmaxf(l0, l1);
            float lse = m + logf(expf(l0 - m) + expf(l1 - m));
            float ly = isqa[b2] ? l1 : l0;
            iloss += lse - ly;
            closs += g_Z[b2] - g_gold[b2];
        }
        out[OFF_ILOSS] = iloss * (1.0f / BB);
        out[OFF_CLOSS] = closs * (1.0f / BB);
    }
}

extern "C" void kernel_launch(void* const* d_in, const int* in_sizes, int n_in,
                              void* d_out, int out_size)
{
    const float* emb  = (const float*)d_in[0];
    const int*   asl  = (const int*)d_in[1];
    const int*   isqa = (const int*)d_in[2];
    const float* fc2W = (const float*)d_in[3];
    const float* fc2b = (const float*)d_in[4];
    const float* crfW = (const float*)d_in[5];
    const float* crfb = (const float*)d_in[6];
    const float* trans = (const float*)d_in[7];
    float* out = (float*)d_out;

    int warps = BB * 129;               // 8256 warps
    int threads = 256;
    int blocks = (warps * 32 + threads - 1) / threads;
    k_feats<<<blocks, threads>>>(emb, fc2W, fc2b, crfW, crfb);
    k_crf<<<128, 32>>>(asl, trans, out);
    k_final<<<(BB * SS + 255) / 256, 256>>>(asl, isqa, out);
}

// round 3
// speedup vs baseline: 1.3422x; 1.1717x over previous
#include <cuda_runtime.h>
#include <math.h>

#define BB 64
#define S1 513
#define SS 512
#define HD 768
#define ST_START 2
#define ST_STOP 3
#define NEGINF (-1e30f)

// ---- scratch ----
__device__ __align__(16) float g_feats[BB * SS * 4];
__device__ float g_logits[BB * 2];
__device__ float g_Z[BB];
__device__ float g_gold[BB];
__device__ int g_done;

// out layout (float32)
#define OFF_PRED   0
#define OFF_CRF    64
#define OFF_ILOSS  32832
#define OFF_CLOSS  32833
#define OFF_TAGS   32834
#define OFF_ISQA   65602

// split-butterfly: 2N values/lane -> N values/lane, partner-reduced.
// After applying with d=16,8,4,2,1 starting at 32 values, lane l holds
// the full 32-lane sum of value index l.
template<int N>
__device__ __forceinline__ void half_reduce(float* v, int lane, int d)
{
    bool up = (lane & d) != 0;
    #pragma unroll
    for (int k = 0; k < N; k++) {
        float send = up ? v[k] : v[k + N];
        float recv = __shfl_xor_sync(~0u, send, d);
        v[k] = (up ? v[k + N] : v[k]) + recv;
    }
}

// =====================================================================
// Kernel 1: feats (8 rows / warp) + cls logits
// =====================================================================
__global__ void __launch_bounds__(256) k_feats(
        const float* __restrict__ emb,
        const float* __restrict__ fc2W, const float* __restrict__ fc2b,
        const float* __restrict__ crfW, const float* __restrict__ crfb)
{
    if (blockIdx.x == 0 && threadIdx.x == 0) g_done = 0;
    int w = (blockIdx.x * blockDim.x + threadIdx.x) >> 5;
    int lane = threadIdx.x & 31;
    if (w >= BB * 65) return;
    int b = w / 65;
    int g = w - b * 65;
    const float4* emb4 = reinterpret_cast<const float4*>(emb);

    if (g == 64) {
        // CLS -> fc2 logits
        const float4* e4 = emb4 + (size_t)(b * S1) * (HD / 4);
        const float4* w0 = reinterpret_cast<const float4*>(fc2W);
        const float4* w1 = w0 + (HD / 4);
        float a0 = 0.f, a1 = 0.f;
        #pragma unroll
        for (int k = 0; k < 6; k++) {
            int idx = k * 32 + lane;
            float4 e = e4[idx];
            float4 x = w0[idx];
            float4 y = w1[idx];
            a0 += e.x * x.x + e.y * x.y + e.z * x.z + e.w * x.w;
            a1 += e.x * y.x + e.y * y.y + e.z * y.z + e.w * y.w;
        }
        #pragma unroll
        for (int off = 16; off; off >>= 1) {
            a0 += __shfl_xor_sync(~0u, a0, off);
            a1 += __shfl_xor_sync(~0u, a1, off);
        }
        if (lane == 0) {
            g_logits[b * 2 + 0] = a0 + fc2b[0];
            g_logits[b * 2 + 1] = a1 + fc2b[1];
        }
    } else {
        const float4* e4 = emb4 + (size_t)(b * S1 + 1 + g * 8) * (HD / 4);
        const float4* wp = reinterpret_cast<const float4*>(crfW);
        float v[32];
        #pragma unroll
        for (int t = 0; t < 32; t++) v[t] = 0.f;

        #pragma unroll
        for (int k = 0; k < 6; k++) {
            int idx = k * 32 + lane;
            float4 w0 = wp[idx];
            float4 w1 = wp[192 + idx];
            float4 w2 = wp[384 + idx];
            float4 w3 = wp[576 + idx];
            #pragma unroll
            for (int r = 0; r < 8; r++) {
                float4 e = e4[r * 192 + idx];
                v[r*4+0] += e.x * w0.x + e.y * w0.y + e.z * w0.z + e.w * w0.w;
                v[r*4+1] += e.x * w1.x + e.y * w1.y + e.z * w1.z + e.w * w1.w;
                v[r*4+2] += e.x * w2.x + e.y * w2.y + e.z * w2.z + e.w * w2.w;
                v[r*4+3] += e.x * w3.x + e.y * w3.y + e.z * w3.z + e.w * w3.w;
            }
        }
        half_reduce<16>(v, lane, 16);
        half_reduce<8>(v, lane, 8);
        half_reduce<4>(v, lane, 4);
        half_reduce<2>(v, lane, 2);
        half_reduce<1>(v, lane, 1);
        // lane holds output index lane = r*4 + t
        g_feats[(b * SS + g * 8) * 4 + lane] = v[0] + __ldg(&crfb[lane & 3]);
    }
}

// ---------- helpers ----------
__device__ __forceinline__ void mp_mul(const float* A, const float* B, float* C)
{
    #pragma unroll
    for (int i = 0; i < 4; i++)
        #pragma unroll
        for (int j = 0; j < 4; j++) {
            float m = A[i*4+0] + B[0*4+j];
            m = fmaxf(m, A[i*4+1] + B[1*4+j]);
            m = fmaxf(m, A[i*4+2] + B[2*4+j]);
            m = fmaxf(m, A[i*4+3] + B[3*4+j]);
            C[i*4+j] = m;
        }
}
__device__ __forceinline__ void lin_mul(const float* A, const float* B, float* C)
{
    #pragma unroll
    for (int i = 0; i < 4; i++)
        #pragma unroll
        for (int j = 0; j < 4; j++)
            C[i*4+j] = A[i*4+0]*B[0*4+j] + A[i*4+1]*B[1*4+j]
                     + A[i*4+2]*B[2*4+j] + A[i*4+3]*B[3*4+j];
}
__device__ __forceinline__ void cp16(float* d, const float* s)
{
    #pragma unroll
    for (int t = 0; t < 16; t++) d[t] = s[t];
}
__device__ __forceinline__ void renorm16(float* M, float& logacc)
{
    float m = M[0];
    #pragma unroll
    for (int t = 1; t < 16; t++) m = fmaxf(m, M[t]);
    float inv = 1.0f / m;
    #pragma unroll
    for (int t = 0; t < 16; t++) M[t] *= inv;
    logacc += __logf(m);
}

// =====================================================================
// Kernel 2: 128 one-warp blocks + fused finalize (last block done)
// =====================================================================
__global__ void __launch_bounds__(32) k_crf(
        const int* __restrict__ asl, const int* __restrict__ isqa_in,
        const float* __restrict__ trans, float* __restrict__ out)
{
    int b = blockIdx.x & 63;
    bool vit = blockIdx.x >= 64;
    int lane = threadIdx.x;

    float T[16];
    #pragma unroll
    for (int t = 0; t < 16; t++) T[t] = __ldg(&trans[t]);

    const float4* F4 = reinterpret_cast<const float4*>(g_feats) + b * SS;

    if (!vit) {
        // ---------- gold ----------
        const int* tg = asl + b * S1 + 1;
        float gpart = 0.f;
        #pragma unroll
        for (int q = 0; q < 16; q++) {
            int i = q * 32 + lane;
            float4 f = F4[i];
            int tc = tg[i];
            gpart += tc ? f.y : f.x;
            float tval;
            if (i == 0) tval = tc ? T[ST_START*4+1] : T[ST_START*4+0];
            else {
                int tp = tg[i - 1];
                tval = tp ? (tc ? T[1*4+1] : T[1*4+0]) : (tc ? T[0*4+1] : T[0*4+0]);
            }
            gpart += tval;
            if (i == SS - 1) gpart += tc ? T[1*4+ST_STOP] : T[0*4+ST_STOP];
        }
        #pragma unroll
        for (int off = 16; off; off >>= 1)
            gpart += __shfl_xor_sync(~0u, gpart, off);
        if (lane == 0) g_gold[b] = gpart;

        // ---------- Z ----------
        float E[16];
        #pragma unroll
        for (int t = 0; t < 16; t++) E[t] = __expf(T[t]);

        float M[16];
        #pragma unroll
        for (int t = 0; t < 16; t++) M[t] = 0.f;
        M[0] = M[5] = M[10] = M[15] = 1.f;
        float logacc = 0.f;

        #pragma unroll
        for (int k = 0; k < 16; k++) {
            int s = lane * 16 + k;
            if (s > 0) {
                float4 f = F4[s];
                float ef[4] = {__expf(f.x), __expf(f.y), __expf(f.z), __expf(f.w)};
                float C[16];
                #pragma unroll
                for (int i = 0; i < 4; i++)
                    #pragma unroll
                    for (int j = 0; j < 4; j++)
                        C[i*4+j] = (M[i*4+0]*E[0*4+j] + M[i*4+1]*E[1*4+j]
                                  + M[i*4+2]*E[2*4+j] + M[i*4+3]*E[3*4+j]) * ef[j];
                cp16(M, C);
                if ((k & 3) == 3) renorm16(M, logacc);
            }
        }
        renorm16(M, logacc);

        #pragma unroll
        for (int d = 1; d < 32; d <<= 1) {
            float O[16];
            #pragma unroll
            for (int t = 0; t < 16; t++) O[t] = __shfl_xor_sync(~0u, M[t], d);
            float ol = __shfl_xor_sync(~0u, logacc, d);
            float C[16];
            if (lane & d) lin_mul(O, M, C);
            else          lin_mul(M, O, C);
            cp16(M, C);
            logacc += ol;
            renorm16(M, logacc);
        }

        if (lane == 0) {
            float4 f0 = F4[0];
            float v0[4] = {__expf(f0.x)*E[ST_START*4+0], __expf(f0.y)*E[ST_START*4+1],
                           __expf(f0.z)*E[ST_START*4+2], __expf(f0.w)*E[ST_START*4+3]};
            float zs = 0.f;
            #pragma unroll
            for (int j = 0; j < 4; j++) {
                float vj = v0[0]*M[0*4+j] + v0[1]*M[1*4+j]
                         + v0[2]*M[2*4+j] + v0[3]*M[3*4+j];
                zs += vj * E[j*4+ST_STOP];
            }
            g_Z[b] = __logf(zs) + logacc;
        }
    } else {
        // ---------- viterbi (register chunks; no smem) ----------
        // tags copy (independent work, also warms asl)
        const int* tg = asl + b * S1 + 1;
        #pragma unroll
        for (int q = 0; q < 16; q++) {
            int i = q * 32 + lane;
            out[OFF_TAGS + b * SS + i] = (float)tg[i];
        }

        // own chunk feats in registers
        float4 ff[16];
        #pragma unroll
        for (int k = 0; k < 16; k++) ff[k] = F4[lane * 16 + k];

        // local max-plus product (A_0 := identity)
        float P[16];
        #pragma unroll
        for (int t = 0; t < 16; t++) P[t] = NEGINF;
        P[0] = P[5] = P[10] = P[15] = 0.f;
        #pragma unroll
        for (int k = 0; k < 16; k++) {
            int s = lane * 16 + k;
            if (s > 0) {
                float4 f = ff[k];
                float C[16];
                #pragma unroll
                for (int i = 0; i < 4; i++) {
                    float m0 = fmaxf(fmaxf(P[i*4+0] + T[0], P[i*4+1] + T[4]),
                                     fmaxf(P[i*4+2] + T[8], P[i*4+3] + T[12]));
                    float m1 = fmaxf(fmaxf(P[i*4+0] + T[1], P[i*4+1] + T[5]),
                                     fmaxf(P[i*4+2] + T[9], P[i*4+3] + T[13]));
                    float m2 = fmaxf(fmaxf(P[i*4+0] + T[2], P[i*4+1] + T[6]),
                                     fmaxf(P[i*4+2] + T[10], P[i*4+3] + T[14]));
                    float m3 = fmaxf(fmaxf(P[i*4+0] + T[3], P[i*4+1] + T[7]),
                                     fmaxf(P[i*4+2] + T[11], P[i*4+3] + T[15]));
                    C[i*4+0] = m0 + f.x; C[i*4+1] = m1 + f.y;
                    C[i*4+2] = m2 + f.z; C[i*4+3] = m3 + f.w;
                }
                cp16(P, C);
            }
        }

        // prefix scan -> exclusive Epre
        float S[16];
        cp16(S, P);
        #pragma unroll
        for (int d = 1; d < 32; d <<= 1) {
            float U[16];
            #pragma unroll
            for (int t = 0; t < 16; t++) U[t] = __shfl_up_sync(~0u, S[t], d);
            if (lane >= d) {
                float C[16];
                mp_mul(U, S, C);
                cp16(S, C);
            }
        }
        float Epre[16];
        #pragma unroll
        for (int t = 0; t < 16; t++) Epre[t] = __shfl_up_sync(~0u, S[t], 1);
        if (lane == 0) {
            #pragma unroll
            for (int t = 0; t < 16; t++) Epre[t] = NEGINF;
            Epre[0] = Epre[5] = Epre[10] = Epre[15] = 0.f;
        }

        // delta at chunk start, then forward emit into registers
        float f0x = __shfl_sync(~0u, ff[0].x, 0);
        float f0y = __shfl_sync(~0u, ff[0].y, 0);
        float f0z = __shfl_sync(~0u, ff[0].z, 0);
        float f0w = __shfl_sync(~0u, ff[0].w, 0);
        float d0[4] = {f0x + T[ST_START*4+0], f0y + T[ST_START*4+1],
                       f0z + T[ST_START*4+2], f0w + T[ST_START*4+3]};
        float v[4];
        #pragma unroll
        for (int j = 0; j < 4; j++) {
            float m = d0[0] + Epre[0*4+j];
            m = fmaxf(m, d0[1] + Epre[1*4+j]);
            m = fmaxf(m, d0[2] + Epre[2*4+j]);
            m = fmaxf(m, d0[3] + Epre[3*4+j]);
            v[j] = m;
        }
        float4 sd[16];
        #pragma unroll
        for (int k = 0; k < 16; k++) {
            int s = lane * 16 + k;
            if (s > 0) {
                float4 f = ff[k];
                float nv0 = fmaxf(fmaxf(v[0]+T[0], v[1]+T[4]), fmaxf(v[2]+T[8],  v[3]+T[12])) + f.x;
                float nv1 = fmaxf(fmaxf(v[0]+T[1], v[1]+T[5]), fmaxf(v[2]+T[9],  v[3]+T[13])) + f.y;
                float nv2 = fmaxf(fmaxf(v[0]+T[2], v[1]+T[6]), fmaxf(v[2]+T[10], v[3]+T[14])) + f.z;
                float nv3 = fmaxf(fmaxf(v[0]+T[3], v[1]+T[7]), fmaxf(v[2]+T[11], v[3]+T[15])) + f.w;
                v[0] = nv0; v[1] = nv1; v[2] = nv2; v[3] = nv3;
            }
            sd[k] = make_float4(v[0], v[1], v[2], v[3]);
        }

        // suffix scan -> exclusive Qex
        cp16(S, P);
        #pragma unroll
        for (int d = 1; d < 32; d <<= 1) {
            float D[16];
            #pragma unroll
            for (int t = 0; t < 16; t++) D[t] = __shfl_down_sync(~0u, S[t], d);
            if (lane + d < 32) {
                float C[16];
                mp_mul(S, D, C);
                cp16(S, C);
            }
        }
        float Qex[16];
        #pragma unroll
        for (int t = 0; t < 16; t++) Qex[t] = __shfl_down_sync(~0u, S[t], 1);
        if (lane == 31) {
            #pragma unroll
            for (int t = 0; t < 16; t++) Qex[t] = NEGINF;
            Qex[0] = Qex[5] = Qex[10] = Qex[15] = 0.f;
        }

        // beta at s = 16*lane+15
        float r0[4] = {T[0*4+ST_STOP], T[1*4+ST_STOP], T[2*4+ST_STOP], T[3*4+ST_STOP]};
        float bb[4];
        #pragma unroll
        for (int i = 0; i < 4; i++) {
            float m = Qex[i*4+0] + r0[0];
            m = fmaxf(m, Qex[i*4+1] + r0[1]);
            m = fmaxf(m, Qex[i*4+2] + r0[2]);
            m = fmaxf(m, Qex[i*4+3] + r0[3]);
            bb[i] = m;
        }

        // backward within chunk: tag = argmax(delta+beta)
        float* po = out + OFF_CRF + b * SS;
        #pragma unroll
        for (int k = 15; k >= 0; k--) {
            float4 dd = sd[k];
            float dv0 = dd.x + bb[0], dv1 = dd.y + bb[1];
            float dv2 = dd.z + bb[2], dv3 = dd.w + bb[3];
            int tsel = 0; float m = dv0;
            if (dv1 > m) { m = dv1; tsel = 1; }
            if (dv2 > m) { m = dv2; tsel = 2; }
            if (dv3 > m) { m = dv3; tsel = 3; }
            po[lane * 16 + k] = (float)tsel;
            if (k > 0) {
                float4 f = ff[k];
                float u0 = f.x + bb[0], u1 = f.y + bb[1];
                float u2 = f.z + bb[2], u3 = f.w + bb[3];
                float nb0 = fmaxf(fmaxf(T[0]+u0,  T[1]+u1),  fmaxf(T[2]+u2,  T[3]+u3));
                float nb1 = fmaxf(fmaxf(T[4]+u0,  T[5]+u1),  fmaxf(T[6]+u2,  T[7]+u3));
                float nb2 = fmaxf(fmaxf(T[8]+u0,  T[9]+u1),  fmaxf(T[10]+u2, T[11]+u3));
                float nb3 = fmaxf(fmaxf(T[12]+u0, T[13]+u1), fmaxf(T[14]+u2, T[15]+u3));
                bb[0] = nb0; bb[1] = nb1; bb[2] = nb2; bb[3] = nb3;
            }
        }
    }

    // ---------- fused finalize: last block to finish does it ----------
    __syncwarp();
    __threadfence();
    int ticket = 0;
    if (lane == 0) ticket = atomicAdd(&g_done, 1);
    ticket = __shfl_sync(~0u, ticket, 0);
    if (ticket == 127) {
        float il = 0.f, cl = 0.f;
        #pragma unroll
        for (int q = 0; q < 2; q++) {
            int bi = lane * 2 + q;
            float l0 = g_logits[bi * 2 + 0];
            float l1 = g_logits[bi * 2 + 1];
            float m = fmaxf(l0, l1);
            float lse = m + __logf(__expf(l0 - m) + __expf(l1 - m));
            int iq = isqa_in[bi];
            il += lse - (iq ? l1 : l0);
            cl += g_Z[bi] - g_gold[bi];
            out[OFF_PRED + bi] = (l1 > l0) ? 1.0f : 0.0f;
            out[OFF_ISQA + bi] = (float)iq;
        }
        #pragma unroll
        for (int off = 16; off; off >>= 1) {
            il += __shfl_xor_sync(~0u, il, off);
            cl += __shfl_xor_sync(~0u, cl, off);
        }
        if (lane == 0) {
            out[OFF_ILOSS] = il * (1.0f / BB);
            out[OFF_CLOSS] = cl * (1.0f / BB);
        }
    }
}

extern "C" void kernel_launch(void* const* d_in, const int* in_sizes, int n_in,
                              void* d_out, int out_size)
{
    const float* emb  = (const float*)d_in[0];
    const int*   asl  = (const int*)d_in[1];
    const int*   isqa = (const int*)d_in[2];
    const float* fc2W = (const float*)d_in[3];
    const float* fc2b = (const float*)d_in[4];
    const float* crfW = (const float*)d_in[5];
    const float* crfb = (const float*)d_in[6];
    const float* trans = (const float*)d_in[7];
    float* out = (float*)d_out;

    int warps = BB * 65;                // 4160 warps
    int threads = 256;
    int blocks = (warps * 32 + threads - 1) / threads;
    k_feats<<<blocks, threads>>>(emb, fc2W, fc2b, crfW, crfb);
    k_crf<<<128, 32>>>(asl, isqa, trans, out);
}

// round 4
// speedup vs baseline: 2.1090x; 1.5713x over previous
#include <cuda_runtime.h>
#include <math.h>

#define BB 64
#define S1 513
#define SS 512
#define HD 768
#define ST_START 2
#define ST_STOP 3
#define NEGINF (-1e30f)

// ---- scratch ----
__device__ __align__(16) float g_feats[BB * SS * 4];
__device__ float g_logits[BB * 2];
__device__ float g_Z[BB];
__device__ float g_gold[BB];
__device__ int g_done;

// out layout (float32)
#define OFF_PRED   0
#define OFF_CRF    64
#define OFF_ILOSS  32832
#define OFF_CLOSS  32833
#define OFF_TAGS   32834
#define OFF_ISQA   65602

template<int N>
__device__ __forceinline__ void half_reduce(float* v, int lane, int d)
{
    bool up = (lane & d) != 0;
    #pragma unroll
    for (int k = 0; k < N; k++) {
        float send = up ? v[k] : v[k + N];
        float recv = __shfl_xor_sync(~0u, send, d);
        v[k] = (up ? v[k + N] : v[k]) + recv;
    }
}

// =====================================================================
// Kernel 1: feats (8 rows / warp) + cls logits   (~LTS-cap bound)
// =====================================================================
__global__ void __launch_bounds__(256) k_feats(
        const float* __restrict__ emb,
        const float* __restrict__ fc2W, const float* __restrict__ fc2b,
        const float* __restrict__ crfW, const float* __restrict__ crfb)
{
    if (blockIdx.x == 0 && threadIdx.x == 0) g_done = 0;
    int w = (blockIdx.x * blockDim.x + threadIdx.x) >> 5;
    int lane = threadIdx.x & 31;
    if (w >= BB * 65) return;
    int b = w / 65;
    int g = w - b * 65;
    const float4* emb4 = reinterpret_cast<const float4*>(emb);

    if (g == 64) {
        const float4* e4 = emb4 + (size_t)(b * S1) * (HD / 4);
        const float4* w0 = reinterpret_cast<const float4*>(fc2W);
        const float4* w1 = w0 + (HD / 4);
        float a0 = 0.f, a1 = 0.f;
        #pragma unroll
        for (int k = 0; k < 6; k++) {
            int idx = k * 32 + lane;
            float4 e = e4[idx];
            float4 x = w0[idx];
            float4 y = w1[idx];
            a0 += e.x * x.x + e.y * x.y + e.z * x.z + e.w * x.w;
            a1 += e.x * y.x + e.y * y.y + e.z * y.z + e.w * y.w;
        }
        #pragma unroll
        for (int off = 16; off; off >>= 1) {
            a0 += __shfl_xor_sync(~0u, a0, off);
            a1 += __shfl_xor_sync(~0u, a1, off);
        }
        if (lane == 0) {
            g_logits[b * 2 + 0] = a0 + fc2b[0];
            g_logits[b * 2 + 1] = a1 + fc2b[1];
        }
    } else {
        const float4* e4 = emb4 + (size_t)(b * S1 + 1 + g * 8) * (HD / 4);
        const float4* wp = reinterpret_cast<const float4*>(crfW);
        float v[32];
        #pragma unroll
        for (int t = 0; t < 32; t++) v[t] = 0.f;

        #pragma unroll
        for (int k = 0; k < 6; k++) {
            int idx = k * 32 + lane;
            float4 w0 = wp[idx];
            float4 w1 = wp[192 + idx];
            float4 w2 = wp[384 + idx];
            float4 w3 = wp[576 + idx];
            #pragma unroll
            for (int r = 0; r < 8; r++) {
                float4 e = e4[r * 192 + idx];
                v[r*4+0] += e.x * w0.x + e.y * w0.y + e.z * w0.z + e.w * w0.w;
                v[r*4+1] += e.x * w1.x + e.y * w1.y + e.z * w1.z + e.w * w1.w;
                v[r*4+2] += e.x * w2.x + e.y * w2.y + e.z * w2.z + e.w * w2.w;
                v[r*4+3] += e.x * w3.x + e.y * w3.y + e.z * w3.z + e.w * w3.w;
            }
        }
        half_reduce<16>(v, lane, 16);
        half_reduce<8>(v, lane, 8);
        half_reduce<4>(v, lane, 4);
        half_reduce<2>(v, lane, 2);
        half_reduce<1>(v, lane, 1);
        g_feats[(b * SS + g * 8) * 4 + lane] = v[0] + __ldg(&crfb[lane & 3]);
    }
}

// ---------- helpers ----------
__device__ __forceinline__ void mp_mul(const float* A, const float* B, float* C)
{
    #pragma unroll
    for (int i = 0; i < 4; i++)
        #pragma unroll
        for (int j = 0; j < 4; j++) {
            float m = A[i*4+0] + B[0*4+j];
            m = fmaxf(m, A[i*4+1] + B[1*4+j]);
            m = fmaxf(m, A[i*4+2] + B[2*4+j]);
            m = fmaxf(m, A[i*4+3] + B[3*4+j]);
            C[i*4+j] = m;
        }
}
__device__ __forceinline__ void lin_mul(const float* A, const float* B, float* C)
{
    #pragma unroll
    for (int i = 0; i < 4; i++)
        #pragma unroll
        for (int j = 0; j < 4; j++)
            C[i*4+j] = A[i*4+0]*B[0*4+j] + A[i*4+1]*B[1*4+j]
                     + A[i*4+2]*B[2*4+j] + A[i*4+3]*B[3*4+j];
}
__device__ __forceinline__ void cp16(float* d, const float* s)
{
    #pragma unroll
    for (int t = 0; t < 16; t++) d[t] = s[t];
}
__device__ __forceinline__ void id_mp(float* M)
{
    #pragma unroll
    for (int t = 0; t < 16; t++) M[t] = NEGINF;
    M[0] = M[5] = M[10] = M[15] = 0.f;
}
__device__ __forceinline__ void renorm16(float* M, float& logacc)
{
    float m = M[0];
    #pragma unroll
    for (int t = 1; t < 16; t++) m = fmaxf(m, M[t]);
    float inv = 1.0f / m;
    #pragma unroll
    for (int t = 0; t < 16; t++) M[t] *= inv;
    logacc += __logf(m);
}

// =====================================================================
// Kernel 2: 128 blocks x 128 threads; chunk = 4 steps/thread.
//   blocks [0,64):   Z (linear semiring) + gold
//   blocks [64,128): viterbi (max-plus prefix+suffix, 2-level scans)
// =====================================================================
__global__ void __launch_bounds__(128) k_crf(
        const int* __restrict__ asl, const int* __restrict__ isqa_in,
        const float* __restrict__ trans, float* __restrict__ out)
{
    int b = blockIdx.x & 63;
    bool vit = blockIdx.x >= 64;
    int tid = threadIdx.x;
    int lane = tid & 31, wid = tid >> 5;

    __shared__ float sW[4][16];   // warp aggregate matrices
    __shared__ float zl[4];
    __shared__ float sg[4];

    float T[16];
    #pragma unroll
    for (int t = 0; t < 16; t++) T[t] = __ldg(&trans[t]);

    const float4* F4 = reinterpret_cast<const float4*>(g_feats) + b * SS;

    if (!vit) {
        // ---------- gold (128 lanes) ----------
        const int* tg = asl + b * S1 + 1;
        float gpart = 0.f;
        #pragma unroll
        for (int q = 0; q < 4; q++) {
            int i = q * 128 + tid;
            float4 f = F4[i];
            int tc = tg[i];
            gpart += tc ? f.y : f.x;
            float tval;
            if (i == 0) tval = tc ? T[ST_START*4+1] : T[ST_START*4+0];
            else {
                int tp = tg[i - 1];
                tval = tp ? (tc ? T[1*4+1] : T[1*4+0]) : (tc ? T[0*4+1] : T[0*4+0]);
            }
            gpart += tval;
            if (i == SS - 1) gpart += tc ? T[1*4+ST_STOP] : T[0*4+ST_STOP];
        }
        #pragma unroll
        for (int off = 16; off; off >>= 1)
            gpart += __shfl_xor_sync(~0u, gpart, off);
        if (lane == 0) sg[wid] = gpart;

        // ---------- Z: local product of 4 matrices ----------
        float E[16];
        #pragma unroll
        for (int t = 0; t < 16; t++) E[t] = __expf(T[t]);

        float M[16];
        #pragma unroll
        for (int t = 0; t < 16; t++) M[t] = 0.f;
        M[0] = M[5] = M[10] = M[15] = 1.f;
        float logacc = 0.f;

        #pragma unroll
        for (int k = 0; k < 4; k++) {
            int s = tid * 4 + k;
            if (s > 0) {
                float4 f = F4[s];
                float ef[4] = {__expf(f.x), __expf(f.y), __expf(f.z), __expf(f.w)};
                float C[16];
                #pragma unroll
                for (int i = 0; i < 4; i++)
                    #pragma unroll
                    for (int j = 0; j < 4; j++)
                        C[i*4+j] = (M[i*4+0]*E[0*4+j] + M[i*4+1]*E[1*4+j]
                                  + M[i*4+2]*E[2*4+j] + M[i*4+3]*E[3*4+j]) * ef[j];
                cp16(M, C);
            }
        }
        renorm16(M, logacc);

        // ordered warp butterfly
        #pragma unroll
        for (int d = 1; d < 32; d <<= 1) {
            float O[16];
            #pragma unroll
            for (int t = 0; t < 16; t++) O[t] = __shfl_xor_sync(~0u, M[t], d);
            float ol = __shfl_xor_sync(~0u, logacc, d);
            float C[16];
            if (lane & d) lin_mul(O, M, C);
            else          lin_mul(M, O, C);
            cp16(M, C);
            logacc += ol;
            renorm16(M, logacc);
        }
        if (lane == 0) {
            #pragma unroll
            for (int t = 0; t < 16; t++) sW[wid][t] = M[t];
            zl[wid] = logacc;
        }
        __syncthreads();
        if (tid == 0) {
            g_gold[b] = sg[0] + sg[1] + sg[2] + sg[3];
            float R[16];
            cp16(R, sW[0]);
            float la = zl[0] + zl[1] + zl[2] + zl[3];
            #pragma unroll
            for (int w2 = 1; w2 < 4; w2++) {
                float C[16];
                lin_mul(R, sW[w2], C);
                cp16(R, C);
                renorm16(R, la);
            }
            float4 f0 = F4[0];
            float v0[4] = {__expf(f0.x)*E[ST_START*4+0], __expf(f0.y)*E[ST_START*4+1],
                           __expf(f0.z)*E[ST_START*4+2], __expf(f0.w)*E[ST_START*4+3]};
            float zs = 0.f;
            #pragma unroll
            for (int j = 0; j < 4; j++) {
                float vj = v0[0]*R[0*4+j] + v0[1]*R[1*4+j]
                         + v0[2]*R[2*4+j] + v0[3]*R[3*4+j];
                zs += vj * E[j*4+ST_STOP];
            }
            g_Z[b] = __logf(zs) + la;
        }
    } else {
        // ---------- viterbi ----------
        const int* tg = asl + b * S1 + 1;
        #pragma unroll
        for (int q = 0; q < 4; q++) {
            int i = q * 128 + tid;
            out[OFF_TAGS + b * SS + i] = (float)tg[i];
        }

        float4 ff[4];
        #pragma unroll
        for (int k = 0; k < 4; k++) ff[k] = F4[tid * 4 + k];

        // local max-plus product (A_0 := identity)
        float P[16];
        id_mp(P);
        #pragma unroll
        for (int k = 0; k < 4; k++) {
            int s = tid * 4 + k;
            if (s > 0) {
                float4 f = ff[k];
                float C[16];
                #pragma unroll
                for (int i = 0; i < 4; i++) {
                    float m0 = fmaxf(fmaxf(P[i*4+0] + T[0],  P[i*4+1] + T[4]),
                                     fmaxf(P[i*4+2] + T[8],  P[i*4+3] + T[12]));
                    float m1 = fmaxf(fmaxf(P[i*4+0] + T[1],  P[i*4+1] + T[5]),
                                     fmaxf(P[i*4+2] + T[9],  P[i*4+3] + T[13]));
                    float m2 = fmaxf(fmaxf(P[i*4+0] + T[2],  P[i*4+1] + T[6]),
                                     fmaxf(P[i*4+2] + T[10], P[i*4+3] + T[14]));
                    float m3 = fmaxf(fmaxf(P[i*4+0] + T[3],  P[i*4+1] + T[7]),
                                     fmaxf(P[i*4+2] + T[11], P[i*4+3] + T[15]));
                    C[i*4+0] = m0 + f.x; C[i*4+1] = m1 + f.y;
                    C[i*4+2] = m2 + f.z; C[i*4+3] = m3 + f.w;
                }
                cp16(P, C);
            }
        }

        // warp inclusive prefix scan
        float S[16];
        cp16(S, P);
        #pragma unroll
        for (int d = 1; d < 32; d <<= 1) {
            float U[16];
            #pragma unroll
            for (int t = 0; t < 16; t++) U[t] = __shfl_up_sync(~0u, S[t], d);
            if (lane >= d) {
                float C[16];
                mp_mul(U, S, C);
                cp16(S, C);
            }
        }
        // warp aggregate (full warp product) -> smem (same for prefix & suffix)
        if (lane == 31) {
            #pragma unroll
            for (int t = 0; t < 16; t++) sW[wid][t] = S[t];
        }
        __syncthreads();

        // full exclusive prefix: Epre = (W_0 ... W_{wid-1}) x Sexcl
        float Sx[16];
        #pragma unroll
        for (int t = 0; t < 16; t++) Sx[t] = __shfl_up_sync(~0u, S[t], 1);
        if (lane == 0) id_mp(Sx);
        float Epre[16];
        {
            float R[16];
            id_mp(R);
            for (int w2 = 0; w2 < wid; w2++) {
                float C[16];
                mp_mul(R, sW[w2], C);
                cp16(R, C);
            }
            mp_mul(R, Sx, Epre);
        }

        // delta at chunk start
        float4 f0 = F4[0];
        float d0[4] = {f0.x + T[ST_START*4+0], f0.y + T[ST_START*4+1],
                       f0.z + T[ST_START*4+2], f0.w + T[ST_START*4+3]};
        float v[4];
        #pragma unroll
        for (int j = 0; j < 4; j++) {
            float m = d0[0] + Epre[0*4+j];
            m = fmaxf(m, d0[1] + Epre[1*4+j]);
            m = fmaxf(m, d0[2] + Epre[2*4+j]);
            m = fmaxf(m, d0[3] + Epre[3*4+j]);
            v[j] = m;
        }
        float4 sd[4];
        #pragma unroll
        for (int k = 0; k < 4; k++) {
            int s = tid * 4 + k;
            if (s > 0) {
                float4 f = ff[k];
                float nv0 = fmaxf(fmaxf(v[0]+T[0], v[1]+T[4]), fmaxf(v[2]+T[8],  v[3]+T[12])) + f.x;
                float nv1 = fmaxf(fmaxf(v[0]+T[1], v[1]+T[5]), fmaxf(v[2]+T[9],  v[3]+T[13])) + f.y;
                float nv2 = fmaxf(fmaxf(v[0]+T[2], v[1]+T[6]), fmaxf(v[2]+T[10], v[3]+T[14])) + f.z;
                float nv3 = fmaxf(fmaxf(v[0]+T[3], v[1]+T[7]), fmaxf(v[2]+T[11], v[3]+T[15])) + f.w;
                v[0] = nv0; v[1] = nv1; v[2] = nv2; v[3] = nv3;
            }
            sd[k] = make_float4(v[0], v[1], v[2], v[3]);
        }

        // warp inclusive suffix scan
        cp16(S, P);
        #pragma unroll
        for (int d = 1; d < 32; d <<= 1) {
            float D[16];
            #pragma unroll
            for (int t = 0; t < 16; t++) D[t] = __shfl_down_sync(~0u, S[t], d);
            if (lane + d < 32) {
                float C[16];
                mp_mul(S, D, C);
                cp16(S, C);
            }
        }
        // full exclusive suffix: Qex = Sexs x (W_{wid+1} ... W_3)
        #pragma unroll
        for (int t = 0; t < 16; t++) Sx[t] = __shfl_down_sync(~0u, S[t], 1);
        if (lane == 31) id_mp(Sx);
        float Qex[16];
        {
            float R[16];
            id_mp(R);
            for (int w2 = wid + 1; w2 < 4; w2++) {
                float C[16];
                mp_mul(R, sW[w2], C);
                cp16(R, C);
            }
            mp_mul(Sx, R, Qex);
        }

        // beta at chunk end
        float r0[4] = {T[0*4+ST_STOP], T[1*4+ST_STOP], T[2*4+ST_STOP], T[3*4+ST_STOP]};
        float bb[4];
        #pragma unroll
        for (int i = 0; i < 4; i++) {
            float m = Qex[i*4+0] + r0[0];
            m = fmaxf(m, Qex[i*4+1] + r0[1]);
            m = fmaxf(m, Qex[i*4+2] + r0[2]);
            m = fmaxf(m, Qex[i*4+3] + r0[3]);
            bb[i] = m;
        }

        // backward within chunk
        float* po = out + OFF_CRF + b * SS;
        #pragma unroll
        for (int k = 3; k >= 0; k--) {
            float4 dd = sd[k];
            float dv0 = dd.x + bb[0], dv1 = dd.y + bb[1];
            float dv2 = dd.z + bb[2], dv3 = dd.w + bb[3];
            int tsel = 0; float m = dv0;
            if (dv1 > m) { m = dv1; tsel = 1; }
            if (dv2 > m) { m = dv2; tsel = 2; }
            if (dv3 > m) { m = dv3; tsel = 3; }
            po[tid * 4 + k] = (float)tsel;
            if (k > 0) {
                float4 f = ff[k];
                float u0 = f.x + bb[0], u1 = f.y + bb[1];
                float u2 = f.z + bb[2], u3 = f.w + bb[3];
                float nb0 = fmaxf(fmaxf(T[0]+u0,  T[1]+u1),  fmaxf(T[2]+u2,  T[3]+u3));
                float nb1 = fmaxf(fmaxf(T[4]+u0,  T[5]+u1),  fmaxf(T[6]+u2,  T[7]+u3));
                float nb2 = fmaxf(fmaxf(T[8]+u0,  T[9]+u1),  fmaxf(T[10]+u2, T[11]+u3));
                float nb3 = fmaxf(fmaxf(T[12]+u0, T[13]+u1), fmaxf(T[14]+u2, T[15]+u3));
                bb[0] = nb0; bb[1] = nb1; bb[2] = nb2; bb[3] = nb3;
            }
        }
    }

    // ---------- fused finalize (last block) ----------
    __syncthreads();
    __threadfence();
    if (wid == 0) {
        int ticket = 0;
        if (lane == 0) ticket = atomicAdd(&g_done, 1);
        ticket = __shfl_sync(~0u, ticket, 0);
        if (ticket == 127) {
            float il = 0.f, cl = 0.f;
            #pragma unroll
            for (int q = 0; q < 2; q++) {
                int bi = lane * 2 + q;
                float l0 = g_logits[bi * 2 + 0];
                float l1 = g_logits[bi * 2 + 1];
                float m = fmaxf(l0, l1);
                float lse = m + __logf(__expf(l0 - m) + __expf(l1 - m));
                int iq = isqa_in[bi];
                il += lse - (iq ? l1 : l0);
                cl += g_Z[bi] - g_gold[bi];
                out[OFF_PRED + bi] = (l1 > l0) ? 1.0f : 0.0f;
                out[OFF_ISQA + bi] = (float)iq;
            }
            #pragma unroll
            for (int off = 16; off; off >>= 1) {
                il += __shfl_xor_sync(~0u, il, off);
                cl += __shfl_xor_sync(~0u, cl, off);
            }
            if (lane == 0) {
                out[OFF_ILOSS] = il * (1.0f / BB);
                out[OFF_CLOSS] = cl * (1.0f / BB);
            }
        }
    }
}

extern "C" void kernel_launch(void* const* d_in, const int* in_sizes, int n_in,
                              void* d_out, int out_size)
{
    const float* emb  = (const float*)d_in[0];
    const int*   asl  = (const int*)d_in[1];
    const int*   isqa = (const int*)d_in[2];
    const float* fc2W = (const float*)d_in[3];
    const float* fc2b = (const float*)d_in[4];
    const float* crfW = (const float*)d_in[5];
    const float* crfb = (const float*)d_in[6];
    const float* trans = (const float*)d_in[7];
    float* out = (float*)d_out;

    int warps = BB * 65;
    int threads = 256;
    int blocks = (warps * 32 + threads - 1) / threads;
    k_feats<<<blocks, threads>>>(emb, fc2W, fc2b, crfW, crfb);
    k_crf<<<128, 128>>>(asl, isqa, trans, out);
}